// round 16
// baseline (speedup 1.0000x reference)
#include <cuda_runtime.h>
#include <cuda_fp16.h>

// APRConv1x1, two K=32 HMMA GEMMs + select (R5/R8/R10/R14 proven core).
// R16 = R14 engine + CONTIGUOUS per-warp tile chunks (was: stride 2368 tiles):
//   each warp owns chunk = ceil(wtiles/slots) consecutive tiles, so its 16
//   read + 16 write DRAM streams advance sequentially 512B/iter over ~7KB
//   -> ~14x fewer row activations per byte; prefetch (wt+1) hits open rows.
// Prefetch = plain float2 regs (R15 lesson: no cvt on the load path).
// Per-point math byte-identical to R14/R10.

#define THREADS 128

__global__ __launch_bounds__(THREADS, 4)
void apr_mma12_kernel(const float* __restrict__ x,
                      const float* __restrict__ Wg,    // [16][16][4]
                      const float* __restrict__ bias,  // [16]
                      const int*   __restrict__ sidx,  // [P]
                      float* __restrict__ out,         // [B][16][N]
                      unsigned Nn, unsigned P, unsigned chunk)
{
    __shared__ __align__(16) char stage[4][8192];   // 64 rows x 128B per warp

    const int tid = threadIdx.x;
    const int wid = tid >> 5;
    const int l   = tid & 31;
    const int t   = l & 3;
    const int r   = l >> 2;

    // ---- once: weight A-fragments (k = 2i + j; W_h[o][2i+j] = Wg[o*64+4i+2h+j]) ----
    unsigned a[2][2][4];
#pragma unroll
    for (int h = 0; h < 2; h++)
#pragma unroll
        for (int ks = 0; ks < 2; ks++) {
            const int i0 = 8 * ks + t;
            const int i1 = 8 * ks + 4 + t;
            float2 w; __half2 hh;
            w = *(const float2*)(Wg + r * 64 + i0 * 4 + 2 * h);
            hh = __floats2half2_rn(w.x, w.y); a[h][ks][0] = *(unsigned*)&hh;
            w = *(const float2*)(Wg + (r + 8) * 64 + i0 * 4 + 2 * h);
            hh = __floats2half2_rn(w.x, w.y); a[h][ks][1] = *(unsigned*)&hh;
            w = *(const float2*)(Wg + r * 64 + i1 * 4 + 2 * h);
            hh = __floats2half2_rn(w.x, w.y); a[h][ks][2] = *(unsigned*)&hh;
            w = *(const float2*)(Wg + (r + 8) * 64 + i1 * 4 + 2 * h);
            hh = __floats2half2_rn(w.x, w.y); a[h][ks][3] = *(unsigned*)&hh;
        }
    const float br0 = __ldg(bias + r);
    const float br8 = __ldg(bias + r + 8);

    const unsigned wtiles = (P + 127) >> 7;
    const unsigned ws     = (unsigned)blockIdx.x * 4u + (unsigned)wid;
    unsigned wt  = ws * chunk;
    if (wt >= wtiles) return;
    unsigned kend = chunk;                       // iterations in my chunk
    if (wt + kend > wtiles) kend = wtiles - wt;

    const unsigned sbase = (unsigned)__cvta_generic_to_shared(stage[wid]);

    // write-side (verified): lane owns rows l and l+32
    const unsigned permw  = (((unsigned)l & 3u) << 1) | (((unsigned)l >> 2) & 1u);
    const unsigned waddr0 = sbase + ((unsigned)l << 7);
    // read-side even/odd 8-row groups (verified R14):
    const unsigned aL   = (unsigned)l & 7u;
    const unsigned ttL  = (unsigned)l >> 3;
    const unsigned slotE = (((ttL ^ (aL & 3u)) << 1) | ((aL >> 2) & 1u));
    const unsigned eaddr0 = sbase + (aL << 7) + (slotE << 4);
    const unsigned oaddr0 = sbase + (aL << 7) + ((slotE ^ 1u) << 4);
    // store row offsets
    const unsigned ro  = (unsigned)r * Nn;
    const unsigned ro8 = (unsigned)(r + 8) * Nn;

    // ---- prologue: load first tile of my chunk ----
    float2 fv0[16], fv1[16]; int2 sv0, sv1;
    {
        unsigned wtb = wt << 7; if (wtb + 128u > P) wtb = P - 128u;
        const unsigned b  = wtb >= Nn ? 1u : 0u;
        const unsigned n0 = wtb - b * Nn;
        const float* xp = x + (size_t)b * 16u * Nn + n0 + 2u * (unsigned)l;
#pragma unroll
        for (int i = 0; i < 16; i++) {
            fv0[i] = *reinterpret_cast<const float2*>(xp + (size_t)((unsigned)i * Nn));
            fv1[i] = *reinterpret_cast<const float2*>(xp + (size_t)((unsigned)i * Nn) + 64u);
        }
        sv0 = *reinterpret_cast<const int2*>(sidx + wtb + 2u * (unsigned)l);
        sv1 = *reinterpret_cast<const int2*>(sidx + wtb + 64u + 2u * (unsigned)l);
    }

    for (unsigned k = 0;;) {
        unsigned wtb = wt << 7; if (wtb + 128u > P) wtb = P - 128u;
        const unsigned b  = wtb >= Nn ? 1u : 0u;
        const unsigned n0 = wtb - b * Nn;
        float* fo = out + (size_t)b * 16u * Nn + n0;

        // current tile's stencil bits + warp-wide select masks
        const int se0 = sv0.x, so0 = sv0.y, se1 = sv1.x, so1 = sv1.y;
        const unsigned be0 = __ballot_sync(0xffffffffu, (se0 >> 1) & 1);
        const unsigned bo0 = __ballot_sync(0xffffffffu, (so0 >> 1) & 1);
        const unsigned be1 = __ballot_sync(0xffffffffu, (se1 >> 1) & 1);
        const unsigned bo1 = __ballot_sync(0xffffffffu, (so1 >> 1) & 1);

        // ---- pack + stage both halves (16x STS.128, conflict-free) ----
        {
            const unsigned she = ((unsigned)se0 & 1u) << 4;
            const unsigned sho = ((unsigned)so0 & 1u) << 4;
#pragma unroll
            for (int cc = 0; cc < 4; cc++) {
                unsigned e0, e1, e2, e3, o0, o1, o2, o3;
                e0 = (unsigned)__half_as_ushort(__float2half(fv0[4*cc+0].x)) << she;
                e1 = (unsigned)__half_as_ushort(__float2half(fv0[4*cc+1].x)) << she;
                e2 = (unsigned)__half_as_ushort(__float2half(fv0[4*cc+2].x)) << she;
                e3 = (unsigned)__half_as_ushort(__float2half(fv0[4*cc+3].x)) << she;
                o0 = (unsigned)__half_as_ushort(__float2half(fv0[4*cc+0].y)) << sho;
                o1 = (unsigned)__half_as_ushort(__float2half(fv0[4*cc+1].y)) << sho;
                o2 = (unsigned)__half_as_ushort(__float2half(fv0[4*cc+2].y)) << sho;
                o3 = (unsigned)__half_as_ushort(__float2half(fv0[4*cc+3].y)) << sho;
                const unsigned ae = waddr0 + ((((unsigned)(2*cc))     ^ permw) << 4);
                const unsigned ao = waddr0 + ((((unsigned)(2*cc + 1)) ^ permw) << 4);
                asm volatile("st.shared.v4.b32 [%0], {%1,%2,%3,%4};"
                             :: "r"(ae), "r"(e0), "r"(e1), "r"(e2), "r"(e3));
                asm volatile("st.shared.v4.b32 [%0], {%1,%2,%3,%4};"
                             :: "r"(ao), "r"(o0), "r"(o1), "r"(o2), "r"(o3));
            }
        }
        {
            const unsigned she = ((unsigned)se1 & 1u) << 4;
            const unsigned sho = ((unsigned)so1 & 1u) << 4;
#pragma unroll
            for (int cc = 0; cc < 4; cc++) {
                unsigned e0, e1, e2, e3, o0, o1, o2, o3;
                e0 = (unsigned)__half_as_ushort(__float2half(fv1[4*cc+0].x)) << she;
                e1 = (unsigned)__half_as_ushort(__float2half(fv1[4*cc+1].x)) << she;
                e2 = (unsigned)__half_as_ushort(__float2half(fv1[4*cc+2].x)) << she;
                e3 = (unsigned)__half_as_ushort(__float2half(fv1[4*cc+3].x)) << she;
                o0 = (unsigned)__half_as_ushort(__float2half(fv1[4*cc+0].y)) << sho;
                o1 = (unsigned)__half_as_ushort(__float2half(fv1[4*cc+1].y)) << sho;
                o2 = (unsigned)__half_as_ushort(__float2half(fv1[4*cc+2].y)) << sho;
                o3 = (unsigned)__half_as_ushort(__float2half(fv1[4*cc+3].y)) << sho;
                const unsigned ae = waddr0 + 4096u + ((((unsigned)(2*cc))     ^ permw) << 4);
                const unsigned ao = waddr0 + 4096u + ((((unsigned)(2*cc + 1)) ^ permw) << 4);
                asm volatile("st.shared.v4.b32 [%0], {%1,%2,%3,%4};"
                             :: "r"(ae), "r"(e0), "r"(e1), "r"(e2), "r"(e3));
                asm volatile("st.shared.v4.b32 [%0], {%1,%2,%3,%4};"
                             :: "r"(ao), "r"(o0), "r"(o1), "r"(o2), "r"(o3));
            }
        }

        // ---- prefetch NEXT (contiguous) tile into the same regs ----
        const bool more = (k + 1u < kend);
        if (more) {
            unsigned wtb2 = (wt + 1u) << 7; if (wtb2 + 128u > P) wtb2 = P - 128u;
            const unsigned b2 = wtb2 >= Nn ? 1u : 0u;
            const unsigned n2 = wtb2 - b2 * Nn;
            const float* xp = x + (size_t)b2 * 16u * Nn + n2 + 2u * (unsigned)l;
#pragma unroll
            for (int i = 0; i < 16; i++) {
                fv0[i] = *reinterpret_cast<const float2*>(xp + (size_t)((unsigned)i * Nn));
                fv1[i] = *reinterpret_cast<const float2*>(xp + (size_t)((unsigned)i * Nn) + 64u);
            }
            sv0 = *reinterpret_cast<const int2*>(sidx + wtb2 + 2u * (unsigned)l);
            sv1 = *reinterpret_cast<const int2*>(sidx + wtb2 + 64u + 2u * (unsigned)l);
        }
        __syncwarp();

        // ---- compute: 8 pairs of (even, odd) groups over rows 8j..8j+7 ----
#pragma unroll
        for (int j = 0; j < 8; j++) {
            const unsigned jo = (unsigned)j << 10;          // 8 rows * 128B

            // --- even-point group: pts 16j + 2c ---
            unsigned b0, b1, b2, b3;
            asm volatile("ldmatrix.sync.aligned.m8n8.x4.shared.b16 {%0,%1,%2,%3}, [%4];"
                         : "=r"(b0), "=r"(b1), "=r"(b2), "=r"(b3) : "r"(eaddr0 + jo));
            float el0 = br0, el1 = br0, el2 = br8, el3 = br8;
            float eh0 = br0, eh1 = br0, eh2 = br8, eh3 = br8;
            asm volatile("mma.sync.aligned.m16n8k16.row.col.f32.f16.f16.f32 "
                "{%0,%1,%2,%3}, {%4,%5,%6,%7}, {%8,%9}, {%0,%1,%2,%3};"
                : "+f"(el0), "+f"(el1), "+f"(el2), "+f"(el3)
                : "r"(a[0][0][0]), "r"(a[0][0][1]), "r"(a[0][0][2]), "r"(a[0][0][3]),
                  "r"(b0), "r"(b1));
            asm volatile("mma.sync.aligned.m16n8k16.row.col.f32.f16.f16.f32 "
                "{%0,%1,%2,%3}, {%4,%5,%6,%7}, {%8,%9}, {%0,%1,%2,%3};"
                : "+f"(el0), "+f"(el1), "+f"(el2), "+f"(el3)
                : "r"(a[0][1][0]), "r"(a[0][1][1]), "r"(a[0][1][2]), "r"(a[0][1][3]),
                  "r"(b2), "r"(b3));
            asm volatile("mma.sync.aligned.m16n8k16.row.col.f32.f16.f16.f32 "
                "{%0,%1,%2,%3}, {%4,%5,%6,%7}, {%8,%9}, {%0,%1,%2,%3};"
                : "+f"(eh0), "+f"(eh1), "+f"(eh2), "+f"(eh3)
                : "r"(a[1][0][0]), "r"(a[1][0][1]), "r"(a[1][0][2]), "r"(a[1][0][3]),
                  "r"(b0), "r"(b1));
            asm volatile("mma.sync.aligned.m16n8k16.row.col.f32.f16.f16.f32 "
                "{%0,%1,%2,%3}, {%4,%5,%6,%7}, {%8,%9}, {%0,%1,%2,%3};"
                : "+f"(eh0), "+f"(eh1), "+f"(eh2), "+f"(eh3)
                : "r"(a[1][1][0]), "r"(a[1][1][1]), "r"(a[1][1][2]), "r"(a[1][1][3]),
                  "r"(b2), "r"(b3));

            const unsigned lam = (unsigned)(8 * (j & 3) + 2 * t);
            const unsigned be  = (j < 4) ? be0 : be1;
            const unsigned bo  = (j < 4) ? bo0 : bo1;
            const float qe0 = ((be >> lam) & 1u)       ? eh0 : el0;
            const float qe1 = ((be >> (lam + 1)) & 1u) ? eh1 : el1;
            const float qe2 = ((be >> lam) & 1u)       ? eh2 : el2;
            const float qe3 = ((be >> (lam + 1)) & 1u) ? eh3 : el3;

            // --- odd-point group: pts 16j + 2c + 1 ---
            asm volatile("ldmatrix.sync.aligned.m8n8.x4.shared.b16 {%0,%1,%2,%3}, [%4];"
                         : "=r"(b0), "=r"(b1), "=r"(b2), "=r"(b3) : "r"(oaddr0 + jo));
            float ol0 = br0, ol1 = br0, ol2 = br8, ol3 = br8;
            float oh0 = br0, oh1 = br0, oh2 = br8, oh3 = br8;
            asm volatile("mma.sync.aligned.m16n8k16.row.col.f32.f16.f16.f32 "
                "{%0,%1,%2,%3}, {%4,%5,%6,%7}, {%8,%9}, {%0,%1,%2,%3};"
                : "+f"(ol0), "+f"(ol1), "+f"(ol2), "+f"(ol3)
                : "r"(a[0][0][0]), "r"(a[0][0][1]), "r"(a[0][0][2]), "r"(a[0][0][3]),
                  "r"(b0), "r"(b1));
            asm volatile("mma.sync.aligned.m16n8k16.row.col.f32.f16.f16.f32 "
                "{%0,%1,%2,%3}, {%4,%5,%6,%7}, {%8,%9}, {%0,%1,%2,%3};"
                : "+f"(ol0), "+f"(ol1), "+f"(ol2), "+f"(ol3)
                : "r"(a[0][1][0]), "r"(a[0][1][1]), "r"(a[0][1][2]), "r"(a[0][1][3]),
                  "r"(b2), "r"(b3));
            asm volatile("mma.sync.aligned.m16n8k16.row.col.f32.f16.f16.f32 "
                "{%0,%1,%2,%3}, {%4,%5,%6,%7}, {%8,%9}, {%0,%1,%2,%3};"
                : "+f"(oh0), "+f"(oh1), "+f"(oh2), "+f"(oh3)
                : "r"(a[1][0][0]), "r"(a[1][0][1]), "r"(a[1][0][2]), "r"(a[1][0][3]),
                  "r"(b0), "r"(b1));
            asm volatile("mma.sync.aligned.m16n8k16.row.col.f32.f16.f16.f32 "
                "{%0,%1,%2,%3}, {%4,%5,%6,%7}, {%8,%9}, {%0,%1,%2,%3};"
                : "+f"(oh0), "+f"(oh1), "+f"(oh2), "+f"(oh3)
                : "r"(a[1][1][0]), "r"(a[1][1][1]), "r"(a[1][1][2]), "r"(a[1][1][3]),
                  "r"(b2), "r"(b3));

            const float qo0 = ((bo >> lam) & 1u)       ? oh0 : ol0;
            const float qo1 = ((bo >> (lam + 1)) & 1u) ? oh1 : ol1;
            const float qo2 = ((bo >> lam) & 1u)       ? oh2 : ol2;
            const float qo3 = ((bo >> (lam + 1)) & 1u) ? oh3 : ol3;

            // --- two direct STG.128: 4 consecutive points per row ---
            const unsigned p0 = (unsigned)(16 * j + 4 * t);
            *reinterpret_cast<float4*>(fo + ro  + p0) = make_float4(qe0, qo0, qe1, qo1);
            *reinterpret_cast<float4*>(fo + ro8 + p0) = make_float4(qe2, qo2, qe3, qo3);
        }
        __syncwarp();   // ldmatrix reads done before next iteration's STS

        if (!more) break;
        wt += 1u; k += 1u;
    }
}

extern "C" void kernel_launch(void* const* d_in, const int* in_sizes, int n_in,
                              void* d_out, int out_size)
{
    const float* x    = (const float*)d_in[0];   // [B, 16, N]
    const float* Wg   = (const float*)d_in[1];   // [16, 16, 4, 1, 1]
    const float* bias = (const float*)d_in[2];   // [16]
    const int*   sidx = (const int*)d_in[3];     // [B, N]

    float* out = (float*)d_out;

    const unsigned P  = (unsigned)in_sizes[3];   // B*N
    const unsigned Nn = P / 2;                   // B = 2

    const unsigned wtiles = (P + 127) / 128;
    const unsigned blk    = 592;                 // 4 CTAs x 148 SMs
    const unsigned slots  = blk * 4;
    const unsigned chunk  = (wtiles + slots - 1) / slots;   // contiguous tiles/warp

    apr_mma12_kernel<<<blk, THREADS>>>(x, Wg, bias, sidx, out, Nn, P, chunk);
}

// round 17
// speedup vs baseline: 1.1177x; 1.1177x over previous
#include <cuda_runtime.h>
#include <cuda_fp16.h>

// APRConv1x1 as FOUR K=16 HMMA GEMMs + 2-bit select (evolved from the proven
// R10 engine; same LDG/prefetch skeleton, interleaved persistent striding).
//   D_s = W[:,:,s] @ x^T  for s=0..3 (A_s in registers), out = D_{s(n)} + bias.
// vs R10's two-K=32-GEMM scatter:
//   - pack is s-INDEPENDENT: 32 cvt.f16x2/lane (was 64 cvt + 64 shift)
//   - stage 4KB/warp: 8 STS.128 (was 16), ldmatrix.x2 (was .x4): ~96 fewer
//     L1 wavefronts/tile, shorter serial chain
//   - 4 independent MMAs/group (was 2 chains of 2 dependent)
// Swizzle: pt p -> row p>>2, chunk (2*(p&3)+kh) ^ (row&7); conflict-free for
// both STS.128 phases and both ldmatrix.x2 phases (derived + checked).

#define THREADS 128

__global__ __launch_bounds__(THREADS, 4)
void apr_mma13_kernel(const float* __restrict__ x,
                      const float* __restrict__ Wg,    // [16][16][4]
                      const float* __restrict__ bias,  // [16]
                      const int*   __restrict__ sidx,  // [P]
                      float* __restrict__ out,         // [B][16][N]
                      unsigned Nn, unsigned P)
{
    __shared__ __align__(16) char stage[4][4096];   // 32 rows x 128B per warp

    const int tid = threadIdx.x;
    const int wid = tid >> 5;
    const int l   = tid & 31;
    const int t   = l & 3;
    const int r   = l >> 2;

    // ---- once: A_s fragments (A_s[o][i] = Wg[o*64 + i*4 + s]), m16n8k16 A ----
    unsigned as[4][4];
#pragma unroll
    for (int s = 0; s < 4; s++) {
        __half2 hh;
        hh = __floats2half2_rn(Wg[r*64 + (2*t)*4 + s],       Wg[r*64 + (2*t+1)*4 + s]);
        as[s][0] = *(unsigned*)&hh;
        hh = __floats2half2_rn(Wg[(r+8)*64 + (2*t)*4 + s],   Wg[(r+8)*64 + (2*t+1)*4 + s]);
        as[s][1] = *(unsigned*)&hh;
        hh = __floats2half2_rn(Wg[r*64 + (2*t+8)*4 + s],     Wg[r*64 + (2*t+9)*4 + s]);
        as[s][2] = *(unsigned*)&hh;
        hh = __floats2half2_rn(Wg[(r+8)*64 + (2*t+8)*4 + s], Wg[(r+8)*64 + (2*t+9)*4 + s]);
        as[s][3] = *(unsigned*)&hh;
    }
    const float br0 = __ldg(bias + r);
    const float br8 = __ldg(bias + r + 8);

    const unsigned wtiles = (P + 127) >> 7;
    const unsigned wstep  = (unsigned)gridDim.x * 4;
    unsigned wt = (unsigned)blockIdx.x * 4 + wid;
    if (wt >= wtiles) return;

    const unsigned sbase = (unsigned)__cvta_generic_to_shared(stage[wid]);

    // write-side: lane owns pts 64h+2l, +1 -> smem row 16h + (l>>1)
    // chunk(j,kh) = (2*((2l+j)&3) + kh) ^ ((l>>1)&7)   (same for both h)
    const unsigned wxor  = ((unsigned)l >> 1) & 7u;
    const unsigned wbase = sbase + (((unsigned)l >> 1) << 7);
    unsigned woff[2][2];
#pragma unroll
    for (int j = 0; j < 2; j++)
#pragma unroll
        for (int kh = 0; kh < 2; kh++)
            woff[j][kh] = ((2u * (((2u * (unsigned)l + (unsigned)j)) & 3u)
                           + (unsigned)kh) ^ wxor) << 4;

    // read-side (ldmatrix.x2): i = l&7, kh = (l>>3)&1
    const unsigned iL  = (unsigned)l & 7u;
    const unsigned khL = ((unsigned)l >> 3) & 1u;
    const unsigned ir2 = iL >> 2;                 // row sub-index
    const unsigned cbL = 2u * (iL & 3u) + khL;    // chunk base
    const unsigned rbase = sbase + (ir2 << 7);

    // store row offsets
    const unsigned ro  = (unsigned)r * Nn;
    const unsigned ro8 = (unsigned)(r + 8) * Nn;

    // ---- prologue: load tile wt (pts 2l,2l+1 and 64+2l,64+2l+1 x 16 ch) ----
    float2 fv0[16], fv1[16]; int2 sv0, sv1;
    {
        unsigned wtb = wt << 7; if (wtb + 128u > P) wtb = P - 128u;
        const unsigned b  = wtb >= Nn ? 1u : 0u;
        const unsigned n0 = wtb - b * Nn;
        const float* xp = x + (size_t)b * 16u * Nn + n0 + 2u * (unsigned)l;
#pragma unroll
        for (int i = 0; i < 16; i++) {
            fv0[i] = *reinterpret_cast<const float2*>(xp + (size_t)((unsigned)i * Nn));
            fv1[i] = *reinterpret_cast<const float2*>(xp + (size_t)((unsigned)i * Nn) + 64u);
        }
        sv0 = *reinterpret_cast<const int2*>(sidx + wtb + 2u * (unsigned)l);
        sv1 = *reinterpret_cast<const int2*>(sidx + wtb + 64u + 2u * (unsigned)l);
    }

    for (;;) {
        unsigned wtb = wt << 7; if (wtb + 128u > P) wtb = P - 128u;
        const unsigned b  = wtb >= Nn ? 1u : 0u;
        const unsigned n0 = wtb - b * Nn;
        float* fo = out + (size_t)b * 16u * Nn + n0;

        // 2-bit select masks for this tile (8 ballots)
        const int se0 = sv0.x, so0 = sv0.y, se1 = sv1.x, so1 = sv1.y;
        const unsigned m0x0 = __ballot_sync(0xffffffffu,  se0       & 1);
        const unsigned m0x1 = __ballot_sync(0xffffffffu, (se0 >> 1) & 1);
        const unsigned m0y0 = __ballot_sync(0xffffffffu,  so0       & 1);
        const unsigned m0y1 = __ballot_sync(0xffffffffu, (so0 >> 1) & 1);
        const unsigned m1x0 = __ballot_sync(0xffffffffu,  se1       & 1);
        const unsigned m1x1 = __ballot_sync(0xffffffffu, (se1 >> 1) & 1);
        const unsigned m1y0 = __ballot_sync(0xffffffffu,  so1       & 1);
        const unsigned m1y1 = __ballot_sync(0xffffffffu, (so1 >> 1) & 1);

        // ---- pack + stage both halves: s-independent cvt.f16x2, 8 STS.128 ----
#pragma unroll
        for (int h = 0; h < 2; h++) {
            const float2* fv = h ? fv1 : fv0;
            const unsigned wb = wbase + ((unsigned)h << 11);   // +2048 for h=1
#pragma unroll
            for (int j = 0; j < 2; j++) {
#pragma unroll
                for (int kh = 0; kh < 2; kh++) {
                    __half2 h0, h1, h2, h3;
                    if (j == 0) {
                        h0 = __floats2half2_rn(fv[kh*8+0].x, fv[kh*8+1].x);
                        h1 = __floats2half2_rn(fv[kh*8+2].x, fv[kh*8+3].x);
                        h2 = __floats2half2_rn(fv[kh*8+4].x, fv[kh*8+5].x);
                        h3 = __floats2half2_rn(fv[kh*8+6].x, fv[kh*8+7].x);
                    } else {
                        h0 = __floats2half2_rn(fv[kh*8+0].y, fv[kh*8+1].y);
                        h1 = __floats2half2_rn(fv[kh*8+2].y, fv[kh*8+3].y);
                        h2 = __floats2half2_rn(fv[kh*8+4].y, fv[kh*8+5].y);
                        h3 = __floats2half2_rn(fv[kh*8+6].y, fv[kh*8+7].y);
                    }
                    asm volatile("st.shared.v4.b32 [%0], {%1,%2,%3,%4};"
                                 :: "r"(wb + woff[j][kh]),
                                    "r"(*(unsigned*)&h0), "r"(*(unsigned*)&h1),
                                    "r"(*(unsigned*)&h2), "r"(*(unsigned*)&h3));
                }
            }
        }

        // ---- prefetch next tile into the SAME registers (WAR after pack) ----
        const unsigned wtn = wt + wstep;
        const bool more = wtn < wtiles;
        if (more) {
            unsigned wtb2 = wtn << 7; if (wtb2 + 128u > P) wtb2 = P - 128u;
            const unsigned b2 = wtb2 >= Nn ? 1u : 0u;
            const unsigned n2 = wtb2 - b2 * Nn;
            const float* xp = x + (size_t)b2 * 16u * Nn + n2 + 2u * (unsigned)l;
#pragma unroll
            for (int i = 0; i < 16; i++) {
                fv0[i] = *reinterpret_cast<const float2*>(xp + (size_t)((unsigned)i * Nn));
                fv1[i] = *reinterpret_cast<const float2*>(xp + (size_t)((unsigned)i * Nn) + 64u);
            }
            sv0 = *reinterpret_cast<const int2*>(sidx + wtb2 + 2u * (unsigned)l);
            sv1 = *reinterpret_cast<const int2*>(sidx + wtb2 + 64u + 2u * (unsigned)l);
        }
        __syncwarp();

        // ---- compute: 16 groups of 8 points, 4 independent MMAs each ----
#pragma unroll
        for (int g = 0; g < 16; g++) {
            const unsigned row  = 2u * (unsigned)g + ir2;
            const unsigned addr = rbase + ((unsigned)g << 8)
                                + ((cbL ^ (row & 7u)) << 4);
            unsigned b0, b1;
            asm volatile("ldmatrix.sync.aligned.m8n8.x2.shared.b16 {%0,%1}, [%2];"
                         : "=r"(b0), "=r"(b1) : "r"(addr));

            float d0[4] = {br0, br0, br8, br8};
            float d1[4] = {br0, br0, br8, br8};
            float d2[4] = {br0, br0, br8, br8};
            float d3[4] = {br0, br0, br8, br8};

            asm volatile("mma.sync.aligned.m16n8k16.row.col.f32.f16.f16.f32 "
                "{%0,%1,%2,%3}, {%4,%5,%6,%7}, {%8,%9}, {%0,%1,%2,%3};"
                : "+f"(d0[0]), "+f"(d0[1]), "+f"(d0[2]), "+f"(d0[3])
                : "r"(as[0][0]), "r"(as[0][1]), "r"(as[0][2]), "r"(as[0][3]),
                  "r"(b0), "r"(b1));
            asm volatile("mma.sync.aligned.m16n8k16.row.col.f32.f16.f16.f32 "
                "{%0,%1,%2,%3}, {%4,%5,%6,%7}, {%8,%9}, {%0,%1,%2,%3};"
                : "+f"(d1[0]), "+f"(d1[1]), "+f"(d1[2]), "+f"(d1[3])
                : "r"(as[1][0]), "r"(as[1][1]), "r"(as[1][2]), "r"(as[1][3]),
                  "r"(b0), "r"(b1));
            asm volatile("mma.sync.aligned.m16n8k16.row.col.f32.f16.f16.f32 "
                "{%0,%1,%2,%3}, {%4,%5,%6,%7}, {%8,%9}, {%0,%1,%2,%3};"
                : "+f"(d2[0]), "+f"(d2[1]), "+f"(d2[2]), "+f"(d2[3])
                : "r"(as[2][0]), "r"(as[2][1]), "r"(as[2][2]), "r"(as[2][3]),
                  "r"(b0), "r"(b1));
            asm volatile("mma.sync.aligned.m16n8k16.row.col.f32.f16.f16.f32 "
                "{%0,%1,%2,%3}, {%4,%5,%6,%7}, {%8,%9}, {%0,%1,%2,%3};"
                : "+f"(d3[0]), "+f"(d3[1]), "+f"(d3[2]), "+f"(d3[3])
                : "r"(as[3][0]), "r"(as[3][1]), "r"(as[3][2]), "r"(as[3][3]),
                  "r"(b0), "r"(b1));

            // 2-bit select: pts 8g+2t (x of owner lane 4(g&7)+t), 8g+2t+1 (y)
            const unsigned idx = (unsigned)(4 * (g & 7) + t);
            const unsigned mx0 = (g < 8) ? m0x0 : m1x0;
            const unsigned mx1 = (g < 8) ? m0x1 : m1x1;
            const unsigned my0 = (g < 8) ? m0y0 : m1y0;
            const unsigned my1 = (g < 8) ? m0y1 : m1y1;
            const bool ex0 = (mx0 >> idx) & 1u, ex1 = (mx1 >> idx) & 1u;
            const bool ey0 = (my0 >> idx) & 1u, ey1 = (my1 >> idx) & 1u;

            const float q0 = ex1 ? (ex0 ? d3[0] : d2[0]) : (ex0 ? d1[0] : d0[0]);
            const float q1 = ey1 ? (ey0 ? d3[1] : d2[1]) : (ey0 ? d1[1] : d0[1]);
            const float q2 = ex1 ? (ex0 ? d3[2] : d2[2]) : (ex0 ? d1[2] : d0[2]);
            const float q3 = ey1 ? (ey0 ? d3[3] : d2[3]) : (ey0 ? d1[3] : d0[3]);

            const unsigned p0 = (unsigned)(8 * g + 2 * t);
            *reinterpret_cast<float2*>(fo + ro  + p0) = make_float2(q0, q1);
            *reinterpret_cast<float2*>(fo + ro8 + p0) = make_float2(q2, q3);
        }
        __syncwarp();   // ldmatrix reads done before next iteration's STS

        if (!more) break;
        wt = wtn;
    }
}

extern "C" void kernel_launch(void* const* d_in, const int* in_sizes, int n_in,
                              void* d_out, int out_size)
{
    const float* x    = (const float*)d_in[0];   // [B, 16, N]
    const float* Wg   = (const float*)d_in[1];   // [16, 16, 4, 1, 1]
    const float* bias = (const float*)d_in[2];   // [16]
    const int*   sidx = (const int*)d_in[3];     // [B, N]

    float* out = (float*)d_out;

    const unsigned P  = (unsigned)in_sizes[3];   // B*N
    const unsigned Nn = P / 2;                   // B = 2

    const unsigned wtiles = (P + 127) / 128;
    unsigned blk = (wtiles + 3) / 4;
    if (blk > 592) blk = 592;                    // 4 CTAs x 148 SMs, persistent

    apr_mma13_kernel<<<blk, THREADS>>>(x, Wg, bias, sidx, out, Nn, P);
}